// round 9
// baseline (speedup 1.0000x reference)
#include <cuda_runtime.h>
#include <math.h>

#define BB 32
#define AA 5
#define CC 80
#define HH 52
#define WW 52
#define NBOX 50
#define HW (HH * WW)          // 2704
#define NCELL_PER_B (AA * HW) // 13520
#define CH (CC + 5)           // 85
#define BLK 256
#define CPT 4
#define CELLS_PER_BLK (BLK * CPT)

__constant__ float c_aw[AA] = {1.3221f, 3.19275f, 5.05587f, 9.47112f, 11.2364f};
__constant__ float c_ah[AA] = {1.73145f, 4.00944f, 8.09892f, 4.84053f, 10.0071f};

static __device__ __forceinline__ float sigmoidf_(float x) {
    return 1.0f / (1.0f + __expf(-x));
}

static __device__ __forceinline__ float warpReduceSum(float v) {
    #pragma unroll
    for (int o = 16; o > 0; o >>= 1) v += __shfl_xor_sync(0xffffffffu, v, o);
    return v;
}
static __device__ __forceinline__ float warpReduceMax(float v) {
    #pragma unroll
    for (int o = 16; o > 0; o >>= 1) v = fmaxf(v, __shfl_xor_sync(0xffffffffu, v, o));
    return v;
}

// ---------------------------------------------------------------------------
// Kernel 1: scatter + correction fused, one block (512 thr) per batch.
// Phase 1: threads 0..49 build gt records + corner table in SHARED only.
// Phase 2: parallel last-writer-wins dedup (n wins iff no j>n same cell).
// Phase 3: 16 warps process winning records: add (true - default) contribution.
// All record traffic stays in shared memory; one atomicAdd per block.
// ---------------------------------------------------------------------------
__global__ __launch_bounds__(512) void scatter_correct_kernel(
    const float* __restrict__ pred, const float* __restrict__ target,
    float* __restrict__ out)
{
    __shared__ float  s_gx1[NBOX], s_gy1[NBOX], s_gx2[NBOX], s_gy2[NBOX], s_a375[NBOX];
    __shared__ int    s_cell[NBOX];   // -1 if invalid
    __shared__ float4 s_tbox[NBOX];
    __shared__ float  s_iou[NBOX];
    __shared__ int    s_cls[NBOX];
    __shared__ int    s_win[NBOX];
    __shared__ float  s_wsum[16];

    const int b    = blockIdx.x;
    const int tid  = threadIdx.x;
    const int lane = tid & 31;
    const int warp = tid >> 5;

    // ---- Phase 1: build records ----
    if (tid < NBOX) {
        const float* t = target + (size_t)(b * NBOX + tid) * 5;
        const float rawx = t[1];
        if (rawx > 0.0f) {
            const float gx = rawx * WW, gy = t[2] * HH;
            const float gw = t[3] * WW, gh = t[4] * HH;

            // corner table for the silence test (identical arithmetic to hot kernel)
            s_gx1[tid]  = gx - 0.5f * gw;
            s_gx2[tid]  = gx + 0.5f * gw;
            s_gy1[tid]  = gy - 0.5f * gh;
            s_gy2[tid]  = gy + 0.5f * gh;
            s_a375[tid] = 0.375f * (gw * gh);

            int   ba   = 0;
            float best = -1.0f;
            #pragma unroll
            for (int a = 0; a < AA; a++) {
                float inter = fminf(gw, c_aw[a]) * fminf(gh, c_ah[a]);
                float uni   = gw * gh + c_aw[a] * c_ah[a] - inter;
                float rr    = inter / uni;
                if (rr > best) { best = rr; ba = a; }
            }

            int gi = (int)gx; gi = gi < 0 ? 0 : (gi > WW - 1 ? WW - 1 : gi);
            int gj = (int)gy; gj = gj < 0 ? 0 : (gj > HH - 1 ? HH - 1 : gj);

            const float* pb = pred + ((size_t)(b * AA + ba) * CH) * HW + gj * WW + gi;
            const float bx = sigmoidf_(pb[0]) + (float)gi;
            const float by = sigmoidf_(pb[HW]) + (float)gj;
            const float bw = __expf(pb[2 * HW]) * c_aw[ba];
            const float bh = __expf(pb[3 * HW]) * c_ah[ba];

            const float iw = fmaxf(fminf(gx + 0.5f * gw, bx + 0.5f * bw) -
                                   fmaxf(gx - 0.5f * gw, bx - 0.5f * bw), 0.0f);
            const float ih = fmaxf(fminf(gy + 0.5f * gh, by + 0.5f * bh) -
                                   fmaxf(gy - 0.5f * gh, by - 0.5f * bh), 0.0f);
            const float inter = iw * ih;
            const float uni   = gw * gh + bw * bh - inter;

            s_cell[tid] = ba * HW + gj * WW + gi;
            s_tbox[tid] = make_float4(gx - (float)gi, gy - (float)gj,
                                      __logf(gw / c_aw[ba]), __logf(gh / c_ah[ba]));
            s_iou[tid]  = inter / uni;
            int tc = (int)t[0]; tc = tc < 0 ? 0 : (tc > CC - 1 ? CC - 1 : tc);
            s_cls[tid]  = tc;
        } else {
            s_cell[tid] = -1;
            s_gx1[tid] = 1e30f;  s_gx2[tid] = -1e30f;
            s_gy1[tid] = 1e30f;  s_gy2[tid] = -1e30f;
            s_a375[tid] = 1e30f;
        }
    }
    __syncthreads();

    // ---- Phase 2: parallel last-writer-wins dedup ----
    if (tid < NBOX) {
        const int mycell = s_cell[tid];
        bool win = (mycell >= 0);
        if (win) {
            for (int j = tid + 1; j < NBOX; j++) win &= (s_cell[j] != mycell);
        }
        s_win[tid] = win ? 1 : 0;
    }
    __syncthreads();

    // ---- Phase 3: per-record correction, warps stride records ----
    float acc = 0.0f;
    for (int rid = warp; rid < NBOX; rid += 16) {
        if (!s_win[rid]) continue;

        const int cell = s_cell[rid];
        const int a  = cell / HW;
        const int r  = cell % HW;
        const int wx = r % WW;
        const int hy = r / WW;

        const float* pb = pred + ((size_t)(b * AA + a) * CH) * HW + r;
        const float q2 = pb[2 * HW], q3 = pb[3 * HW];
        const float sx = sigmoidf_(pb[0]), sy = sigmoidf_(pb[HW]);
        const float cf = sigmoidf_(pb[4 * HW]);
        const float bw = __expf(q2) * c_aw[a], bh = __expf(q3) * c_ah[a];
        const float bx = sx + (float)wx, by = sy + (float)hy;

        const float px1 = bx - 0.5f * bw, px2 = bx + 0.5f * bw;
        const float py1 = by - 0.5f * bh, py2 = by + 0.5f * bh;
        const float t0  = 0.375f * (bw * bh);

        // silence test from shared corner table (lanes stride boxes)
        float m = -1e30f;
        for (int n = lane; n < NBOX; n += 32) {
            float iw = fminf(px2, s_gx2[n]) - fmaxf(px1, s_gx1[n]);
            float ih = fminf(py2, s_gy2[n]) - fmaxf(py1, s_gy1[n]);
            m = fmaxf(m, __fmaf_rn(fmaxf(iw, 0.0f), fmaxf(ih, 0.0f), -s_a375[n]));
        }
        m = warpReduceMax(m);
        const float mask_def = (m > t0) ? 0.0f : 1.0f;

        const float dx0 = sx - 0.5f, dy0 = sy - 0.5f;
        const float v_def = 0.5f * (dx0 * dx0 + dy0 * dy0 + q2 * q2 + q3 * q3 +
                                    cf * cf * mask_def);

        // true contribution
        const float4 tb   = s_tbox[rid];
        const float  tcnf = s_iou[rid];
        const int    tc   = s_cls[rid];

        // 80-way log-softmax CE, lanes stride classes
        const float* cl = pb + 5 * HW;
        float mx = -1e30f;
        for (int c = lane; c < CC; c += 32) mx = fmaxf(mx, cl[c * HW]);
        mx = warpReduceMax(mx);
        float s = 0.0f;
        for (int c = lane; c < CC; c += 32) s += __expf(cl[c * HW] - mx);
        s = warpReduceSum(s);
        const float ce = mx + __logf(s) - cl[tc * HW];

        const float dx = sx - tb.x, dy = sy - tb.y;
        const float dw = q2 - tb.z, dh = q3 - tb.w;
        const float dc = cf - tcnf;
        const float v_true = 0.5f * (dx * dx + dy * dy + dw * dw + dh * dh +
                                     dc * dc * 5.0f) + ce;

        if (lane == 0) acc += v_true - v_def;
    }

    // block reduce -> one atomicAdd per block
    float wv = warpReduceSum(acc);
    if (lane == 0) s_wsum[warp] = wv;
    __syncthreads();
    if (warp == 0) {
        float bv = (lane < 16) ? s_wsum[lane] : 0.0f;
        bv = warpReduceSum(bv);
        if (lane == 0) atomicAdd(out, bv);
    }
}

// ---------------------------------------------------------------------------
// Kernel 2 (HOT): default-target loss for every cell, 4 cells/thread.
// silenced <=> m > 0.375*parea.
// ---------------------------------------------------------------------------
__global__ __launch_bounds__(BLK) void default_loss_kernel(
    const float* __restrict__ pred, const float* __restrict__ target,
    float* __restrict__ out)
{
    __shared__ float4 s_box[NBOX];   // (x1, y1, x2, y2)
    __shared__ float  s_a375[NBOX];  // 0.375 * garea

    const int b   = blockIdx.y;
    const int tid = threadIdx.x;

    if (tid < NBOX) {
        const float* t = target + (size_t)(b * NBOX + tid) * 5;
        float x = t[1] * WW, y = t[2] * HH, w = t[3] * WW, h = t[4] * HH;
        if (t[1] > 0.0f) {
            s_box[tid]  = make_float4(x - 0.5f * w, y - 0.5f * h,
                                      x + 0.5f * w, y + 0.5f * h);
            s_a375[tid] = 0.375f * (w * h);
        } else {
            s_box[tid]  = make_float4(1e30f, 1e30f, -1e30f, -1e30f);
            s_a375[tid] = 1e30f;
        }
    }
    __syncthreads();

    const int base = blockIdx.x * CELLS_PER_BLK;

    bool  ok[CPT];
    float sx[CPT], sy[CPT], q2[CPT], q3[CPT], cf[CPT];
    float px1[CPT], px2[CPT], py1[CPT], py2[CPT], t0[CPT], m[CPT];

    #pragma unroll
    for (int k = 0; k < CPT; k++) {
        const int idx = base + tid + k * BLK;
        ok[k] = idx < NCELL_PER_B;
        const int ci = ok[k] ? idx : 0;
        const int a = ci / HW, r = ci % HW;

        const float* pb = pred + ((size_t)(b * AA + a) * CH) * HW + r;
        q2[k] = pb[2 * HW];
        q3[k] = pb[3 * HW];
        sx[k] = sigmoidf_(pb[0]);
        sy[k] = sigmoidf_(pb[HW]);
        cf[k] = sigmoidf_(pb[4 * HW]);

        const float bw = __expf(q2[k]) * c_aw[a];
        const float bh = __expf(q3[k]) * c_ah[a];
        const float bx = sx[k] + (float)(r % WW);
        const float by = sy[k] + (float)(r / WW);

        px1[k] = bx - 0.5f * bw;  px2[k] = bx + 0.5f * bw;
        py1[k] = by - 0.5f * bh;  py2[k] = by + 0.5f * bh;
        t0[k]  = 0.375f * (bw * bh);
        m[k]   = -1e30f;
    }

    #pragma unroll 5
    for (int n = 0; n < NBOX; n++) {
        const float4 bx4 = s_box[n];
        const float  an  = s_a375[n];
        #pragma unroll
        for (int k = 0; k < CPT; k++) {
            float iw = fminf(px2[k], bx4.z) - fmaxf(px1[k], bx4.x);
            float ih = fminf(py2[k], bx4.w) - fmaxf(py1[k], bx4.y);
            m[k] = fmaxf(m[k], __fmaf_rn(fmaxf(iw, 0.0f), fmaxf(ih, 0.0f), -an));
        }
    }

    float v = 0.0f;
    #pragma unroll
    for (int k = 0; k < CPT; k++) {
        if (ok[k]) {
            const float mask = (m[k] > t0[k]) ? 0.0f : 1.0f;
            const float dx = sx[k] - 0.5f, dy = sy[k] - 0.5f;
            v += 0.5f * (dx * dx + dy * dy + q2[k] * q2[k] + q3[k] * q3[k] +
                         cf[k] * cf[k] * mask);
        }
    }

    __shared__ float s_warp[BLK / 32];
    float wv = warpReduceSum(v);
    const int lane = tid & 31, wid = tid >> 5;
    if (lane == 0) s_warp[wid] = wv;
    __syncthreads();
    if (wid == 0) {
        float bv = (lane < (BLK >> 5)) ? s_warp[lane] : 0.0f;
        bv = warpReduceSum(bv);
        if (lane == 0) atomicAdd(out, bv);
    }
}

extern "C" void kernel_launch(void* const* d_in, const int* in_sizes, int n_in,
                              void* d_out, int out_size)
{
    const float* pred   = (const float*)d_in[0];
    const float* target = (const float*)d_in[1];
    float* out = (float*)d_out;

    cudaMemsetAsync(out, 0, (size_t)out_size * sizeof(float));

    scatter_correct_kernel<<<BB, 512>>>(pred, target, out);

    dim3 grid((NCELL_PER_B + CELLS_PER_BLK - 1) / CELLS_PER_BLK, BB);
    default_loss_kernel<<<grid, BLK>>>(pred, target, out);
}

// round 10
// speedup vs baseline: 1.1661x; 1.1661x over previous
#include <cuda_runtime.h>
#include <math.h>

#define BB 32
#define AA 5
#define CC 80
#define HH 52
#define WW 52
#define NBOX 50
#define HW (HH * WW)          // 2704
#define NCELL_PER_B (AA * HW) // 13520
#define CH (CC + 5)           // 85
#define BLK 256
#define CPT 2
#define CELLS_PER_BLK (BLK * CPT)                 // 512
#define HOT_BLOCKS_PER_B ((NCELL_PER_B + CELLS_PER_BLK - 1) / CELLS_PER_BLK)  // 27
#define TOTAL_BLOCKS (BB + BB * HOT_BLOCKS_PER_B) // 32 + 864 = 896

__constant__ float c_aw[AA] = {1.3221f, 3.19275f, 5.05587f, 9.47112f, 11.2364f};
__constant__ float c_ah[AA] = {1.73145f, 4.00944f, 8.09892f, 4.84053f, 10.0071f};

static __device__ __forceinline__ float sigmoidf_(float x) {
    return 1.0f / (1.0f + __expf(-x));
}

static __device__ __forceinline__ float warpReduceSum(float v) {
    #pragma unroll
    for (int o = 16; o > 0; o >>= 1) v += __shfl_xor_sync(0xffffffffu, v, o);
    return v;
}
static __device__ __forceinline__ float warpReduceMax(float v) {
    #pragma unroll
    for (int o = 16; o > 0; o >>= 1) v = fmaxf(v, __shfl_xor_sync(0xffffffffu, v, o));
    return v;
}

// ---------------------------------------------------------------------------
// ONE kernel, two block roles (independent; overlap on the SM array):
//   blocks [0, BB)            : scatter + dedup + correction for batch b
//   blocks [BB, TOTAL_BLOCKS) : default-target loss, CPT=2 cells/thread
// Both roles end in one atomicAdd(out) per block.
// ---------------------------------------------------------------------------
__global__ __launch_bounds__(BLK) void region_loss_kernel(
    const float* __restrict__ pred, const float* __restrict__ target,
    float* __restrict__ out)
{
    // shared: union of both roles' needs (allocated unconditionally; ~4KB)
    __shared__ float  s_gx1[NBOX], s_gy1[NBOX], s_gx2[NBOX], s_gy2[NBOX], s_a375[NBOX];
    __shared__ int    s_cell[NBOX];
    __shared__ float4 s_tbox[NBOX];
    __shared__ float  s_iou[NBOX];
    __shared__ int    s_cls[NBOX];
    __shared__ int    s_win[NBOX];
    __shared__ float  s_red[BLK / 32];

    const int tid  = threadIdx.x;
    const int lane = tid & 31;
    const int warp = tid >> 5;

    if (blockIdx.x < BB) {
        // =================== ROLE A: scatter + correction ===================
        const int b = blockIdx.x;

        // ---- Phase 1: build records + gt corner table (threads 0..49) ----
        if (tid < NBOX) {
            const float* t = target + (size_t)(b * NBOX + tid) * 5;
            const float rawx = t[1];
            if (rawx > 0.0f) {
                const float gx = rawx * WW, gy = t[2] * HH;
                const float gw = t[3] * WW, gh = t[4] * HH;

                s_gx1[tid]  = gx - 0.5f * gw;
                s_gx2[tid]  = gx + 0.5f * gw;
                s_gy1[tid]  = gy - 0.5f * gh;
                s_gy2[tid]  = gy + 0.5f * gh;
                s_a375[tid] = 0.375f * (gw * gh);

                int   ba   = 0;
                float best = -1.0f;
                #pragma unroll
                for (int a = 0; a < AA; a++) {
                    float inter = fminf(gw, c_aw[a]) * fminf(gh, c_ah[a]);
                    float uni   = gw * gh + c_aw[a] * c_ah[a] - inter;
                    float rr    = inter / uni;
                    if (rr > best) { best = rr; ba = a; }
                }

                int gi = (int)gx; gi = gi < 0 ? 0 : (gi > WW - 1 ? WW - 1 : gi);
                int gj = (int)gy; gj = gj < 0 ? 0 : (gj > HH - 1 ? HH - 1 : gj);

                const float* pb = pred + ((size_t)(b * AA + ba) * CH) * HW + gj * WW + gi;
                const float bx = sigmoidf_(pb[0]) + (float)gi;
                const float by = sigmoidf_(pb[HW]) + (float)gj;
                const float bw = __expf(pb[2 * HW]) * c_aw[ba];
                const float bh = __expf(pb[3 * HW]) * c_ah[ba];

                const float iw = fmaxf(fminf(gx + 0.5f * gw, bx + 0.5f * bw) -
                                       fmaxf(gx - 0.5f * gw, bx - 0.5f * bw), 0.0f);
                const float ih = fmaxf(fminf(gy + 0.5f * gh, by + 0.5f * bh) -
                                       fmaxf(gy - 0.5f * gh, by - 0.5f * bh), 0.0f);
                const float inter = iw * ih;
                const float uni   = gw * gh + bw * bh - inter;

                s_cell[tid] = ba * HW + gj * WW + gi;
                s_tbox[tid] = make_float4(gx - (float)gi, gy - (float)gj,
                                          __logf(gw / c_aw[ba]), __logf(gh / c_ah[ba]));
                s_iou[tid]  = inter / uni;
                int tc = (int)t[0]; tc = tc < 0 ? 0 : (tc > CC - 1 ? CC - 1 : tc);
                s_cls[tid]  = tc;
            } else {
                s_cell[tid] = -1;
                s_gx1[tid] = 1e30f;  s_gx2[tid] = -1e30f;
                s_gy1[tid] = 1e30f;  s_gy2[tid] = -1e30f;
                s_a375[tid] = 1e30f;
            }
        }
        __syncthreads();

        // ---- Phase 2: parallel last-writer-wins dedup ----
        if (tid < NBOX) {
            const int mycell = s_cell[tid];
            bool win = (mycell >= 0);
            if (win) {
                for (int j = tid + 1; j < NBOX; j++) win &= (s_cell[j] != mycell);
            }
            s_win[tid] = win ? 1 : 0;
        }
        __syncthreads();

        // ---- Phase 3: per-record correction, 8 warps stride records ----
        float acc = 0.0f;
        for (int rid = warp; rid < NBOX; rid += BLK / 32) {
            if (!s_win[rid]) continue;

            const int cell = s_cell[rid];
            const int a  = cell / HW;
            const int r  = cell % HW;

            const float* pb = pred + ((size_t)(b * AA + a) * CH) * HW + r;
            const float q2 = pb[2 * HW], q3 = pb[3 * HW];
            const float sx = sigmoidf_(pb[0]), sy = sigmoidf_(pb[HW]);
            const float cf = sigmoidf_(pb[4 * HW]);
            const float bw = __expf(q2) * c_aw[a], bh = __expf(q3) * c_ah[a];
            const float bx = sx + (float)(r % WW), by = sy + (float)(r / WW);

            const float px1 = bx - 0.5f * bw, px2 = bx + 0.5f * bw;
            const float py1 = by - 0.5f * bh, py2 = by + 0.5f * bh;
            const float t0  = 0.375f * (bw * bh);

            // silence test (identical arithmetic to hot role; fmax exact)
            float m = -1e30f;
            for (int n = lane; n < NBOX; n += 32) {
                float iw = fminf(px2, s_gx2[n]) - fmaxf(px1, s_gx1[n]);
                float ih = fminf(py2, s_gy2[n]) - fmaxf(py1, s_gy1[n]);
                m = fmaxf(m, __fmaf_rn(fmaxf(iw, 0.0f), fmaxf(ih, 0.0f), -s_a375[n]));
            }
            m = warpReduceMax(m);
            const float mask_def = (m > t0) ? 0.0f : 1.0f;

            const float dx0 = sx - 0.5f, dy0 = sy - 0.5f;
            const float v_def = 0.5f * (dx0 * dx0 + dy0 * dy0 + q2 * q2 + q3 * q3 +
                                        cf * cf * mask_def);

            const float4 tb   = s_tbox[rid];
            const float  tcnf = s_iou[rid];
            const int    tc   = s_cls[rid];

            // 80-way log-softmax CE, lanes stride classes
            const float* cl = pb + 5 * HW;
            float mx = -1e30f;
            for (int c = lane; c < CC; c += 32) mx = fmaxf(mx, cl[c * HW]);
            mx = warpReduceMax(mx);
            float s = 0.0f;
            for (int c = lane; c < CC; c += 32) s += __expf(cl[c * HW] - mx);
            s = warpReduceSum(s);
            const float ce = mx + __logf(s) - cl[tc * HW];

            const float dx = sx - tb.x, dy = sy - tb.y;
            const float dw = q2 - tb.z, dh = q3 - tb.w;
            const float dc = cf - tcnf;
            const float v_true = 0.5f * (dx * dx + dy * dy + dw * dw + dh * dh +
                                         dc * dc * 5.0f) + ce;

            if (lane == 0) acc += v_true - v_def;
        }

        float wv = warpReduceSum(acc);
        if (lane == 0) s_red[warp] = wv;
        __syncthreads();
        if (warp == 0) {
            float bv = (lane < (BLK / 32)) ? s_red[lane] : 0.0f;
            bv = warpReduceSum(bv);
            if (lane == 0) atomicAdd(out, bv);
        }
        return;
    }

    // ===================== ROLE B: default-target loss =====================
    const int gid   = blockIdx.x - BB;
    const int b     = gid / HOT_BLOCKS_PER_B;
    const int chunk = gid % HOT_BLOCKS_PER_B;

    // gt corner table (float4 box + area), loaded by threads 0..49
    if (tid < NBOX) {
        const float* t = target + (size_t)(b * NBOX + tid) * 5;
        float x = t[1] * WW, y = t[2] * HH, w = t[3] * WW, h = t[4] * HH;
        if (t[1] > 0.0f) {
            s_gx1[tid]  = x - 0.5f * w;
            s_gy1[tid]  = y - 0.5f * h;
            s_gx2[tid]  = x + 0.5f * w;
            s_gy2[tid]  = y + 0.5f * h;
            s_a375[tid] = 0.375f * (w * h);
        } else {
            s_gx1[tid] = 1e30f;  s_gx2[tid] = -1e30f;
            s_gy1[tid] = 1e30f;  s_gy2[tid] = -1e30f;
            s_a375[tid] = 1e30f;
        }
    }
    // pack into float4 for single-LDS.128 access in the loop
    __syncthreads();
    if (tid < NBOX) {
        s_tbox[tid] = make_float4(s_gx1[tid], s_gy1[tid], s_gx2[tid], s_gy2[tid]);
    }
    __syncthreads();

    const int base = chunk * CELLS_PER_BLK;

    const int idx0 = base + tid;
    const int idx1 = base + tid + BLK;
    const bool ok0 = idx0 < NCELL_PER_B;
    const bool ok1 = idx1 < NCELL_PER_B;
    const int ci0 = ok0 ? idx0 : 0;
    const int ci1 = ok1 ? idx1 : 0;

    const int a0 = ci0 / HW, r0 = ci0 % HW;
    const int a1 = ci1 / HW, r1 = ci1 % HW;

    const float* pb0 = pred + ((size_t)(b * AA + a0) * CH) * HW + r0;
    const float* pb1 = pred + ((size_t)(b * AA + a1) * CH) * HW + r1;

    const float q02 = pb0[2 * HW], q03 = pb0[3 * HW];
    const float q12 = pb1[2 * HW], q13 = pb1[3 * HW];

    const float sx0 = sigmoidf_(pb0[0]), sy0 = sigmoidf_(pb0[HW]);
    const float sx1 = sigmoidf_(pb1[0]), sy1 = sigmoidf_(pb1[HW]);
    const float cf0 = sigmoidf_(pb0[4 * HW]);
    const float cf1 = sigmoidf_(pb1[4 * HW]);

    const float bw0 = __expf(q02) * c_aw[a0], bh0 = __expf(q03) * c_ah[a0];
    const float bw1 = __expf(q12) * c_aw[a1], bh1 = __expf(q13) * c_ah[a1];

    const float bx0 = sx0 + (float)(r0 % WW), by0 = sy0 + (float)(r0 / WW);
    const float bx1 = sx1 + (float)(r1 % WW), by1 = sy1 + (float)(r1 / WW);

    const float px1_0 = bx0 - 0.5f * bw0, px2_0 = bx0 + 0.5f * bw0;
    const float py1_0 = by0 - 0.5f * bh0, py2_0 = by0 + 0.5f * bh0;
    const float px1_1 = bx1 - 0.5f * bw1, px2_1 = bx1 + 0.5f * bw1;
    const float py1_1 = by1 - 0.5f * bh1, py2_1 = by1 + 0.5f * bh1;
    const float t0_0 = 0.375f * (bw0 * bh0);
    const float t0_1 = 0.375f * (bw1 * bh1);

    float m0 = -1e30f, m1 = -1e30f;
    #pragma unroll 10
    for (int n = 0; n < NBOX; n++) {
        const float4 bx4 = s_tbox[n];     // (x1, y1, x2, y2)
        const float  an  = s_a375[n];

        float iw0 = fminf(px2_0, bx4.z) - fmaxf(px1_0, bx4.x);
        float ih0 = fminf(py2_0, bx4.w) - fmaxf(py1_0, bx4.y);
        m0 = fmaxf(m0, __fmaf_rn(fmaxf(iw0, 0.0f), fmaxf(ih0, 0.0f), -an));

        float iw1 = fminf(px2_1, bx4.z) - fmaxf(px1_1, bx4.x);
        float ih1 = fminf(py2_1, bx4.w) - fmaxf(py1_1, bx4.y);
        m1 = fmaxf(m1, __fmaf_rn(fmaxf(iw1, 0.0f), fmaxf(ih1, 0.0f), -an));
    }

    float v = 0.0f;
    if (ok0) {
        const float mask = (m0 > t0_0) ? 0.0f : 1.0f;
        const float dx = sx0 - 0.5f, dy = sy0 - 0.5f;
        v += 0.5f * (dx * dx + dy * dy + q02 * q02 + q03 * q03 + cf0 * cf0 * mask);
    }
    if (ok1) {
        const float mask = (m1 > t0_1) ? 0.0f : 1.0f;
        const float dx = sx1 - 0.5f, dy = sy1 - 0.5f;
        v += 0.5f * (dx * dx + dy * dy + q12 * q12 + q13 * q13 + cf1 * cf1 * mask);
    }

    float wv = warpReduceSum(v);
    if (lane == 0) s_red[warp] = wv;
    __syncthreads();
    if (warp == 0) {
        float bv = (lane < (BLK / 32)) ? s_red[lane] : 0.0f;
        bv = warpReduceSum(bv);
        if (lane == 0) atomicAdd(out, bv);
    }
}

extern "C" void kernel_launch(void* const* d_in, const int* in_sizes, int n_in,
                              void* d_out, int out_size)
{
    const float* pred   = (const float*)d_in[0];
    const float* target = (const float*)d_in[1];
    float* out = (float*)d_out;

    cudaMemsetAsync(out, 0, (size_t)out_size * sizeof(float));
    region_loss_kernel<<<TOTAL_BLOCKS, BLK>>>(pred, target, out);
}

// round 12
// speedup vs baseline: 1.5246x; 1.3074x over previous
#include <cuda_runtime.h>
#include <math.h>

#define BB 32
#define AA 5
#define CC 80
#define HH 52
#define WW 52
#define NBOX 50
#define HW (HH * WW)          // 2704
#define NCELL_PER_B (AA * HW) // 13520
#define CH (CC + 5)           // 85
#define BLK 256
#define CPT 2
#define CELLS_PER_BLK (BLK * CPT)                 // 512
#define HOT_BLOCKS_PER_B ((NCELL_PER_B + CELLS_PER_BLK - 1) / CELLS_PER_BLK)  // 27
#define SCAT_SPLIT 4
#define SCAT_BLOCKS (BB * SCAT_SPLIT)             // 128
#define TOTAL_BLOCKS (SCAT_BLOCKS + BB * HOT_BLOCKS_PER_B) // 128 + 864 = 992

__constant__ float c_aw[AA] = {1.3221f, 3.19275f, 5.05587f, 9.47112f, 11.2364f};
__constant__ float c_ah[AA] = {1.73145f, 4.00944f, 8.09892f, 4.84053f, 10.0071f};

static __device__ __forceinline__ float sigmoidf_(float x) {
    return 1.0f / (1.0f + __expf(-x));
}

static __device__ __forceinline__ float warpReduceSum(float v) {
    #pragma unroll
    for (int o = 16; o > 0; o >>= 1) v += __shfl_xor_sync(0xffffffffu, v, o);
    return v;
}
static __device__ __forceinline__ float warpReduceMax(float v) {
    #pragma unroll
    for (int o = 16; o > 0; o >>= 1) v = fmaxf(v, __shfl_xor_sync(0xffffffffu, v, o));
    return v;
}

// ---------------------------------------------------------------------------
// ONE kernel, two block roles (independent; overlap on the SM array):
//   blocks [0, SCAT_BLOCKS)   : scatter + dedup + correction; 4 blocks/batch,
//                               records split by rid % SCAT_SPLIT
//   blocks [SCAT_BLOCKS, ...) : default-target loss, CPT=2 cells/thread
// Both roles end in one atomicAdd(out) per block.
// ---------------------------------------------------------------------------
__global__ __launch_bounds__(BLK) void region_loss_kernel(
    const float* __restrict__ pred, const float* __restrict__ target,
    float* __restrict__ out)
{
    __shared__ float4 s_box[NBOX];    // (x1, y1, x2, y2)
    __shared__ float  s_a375[NBOX];   // 0.375 * garea
    __shared__ int    s_cell[NBOX];
    __shared__ float4 s_tbox[NBOX];
    __shared__ float  s_iou[NBOX];
    __shared__ int    s_cls[NBOX];
    __shared__ int    s_win[NBOX];
    __shared__ float  s_red[BLK / 32];

    const int tid  = threadIdx.x;
    const int lane = tid & 31;
    const int warp = tid >> 5;

    if (blockIdx.x < SCAT_BLOCKS) {
        // =================== ROLE A: scatter + correction ===================
        const int b   = blockIdx.x / SCAT_SPLIT;
        const int sub = blockIdx.x % SCAT_SPLIT;

        // ---- Phase 1: build records + gt corner table (threads 0..49) ----
        if (tid < NBOX) {
            const float* t = target + (size_t)(b * NBOX + tid) * 5;
            const float rawx = t[1];
            if (rawx > 0.0f) {
                const float gx = rawx * WW, gy = t[2] * HH;
                const float gw = t[3] * WW, gh = t[4] * HH;

                s_box[tid]  = make_float4(gx - 0.5f * gw, gy - 0.5f * gh,
                                          gx + 0.5f * gw, gy + 0.5f * gh);
                s_a375[tid] = 0.375f * (gw * gh);

                int   ba   = 0;
                float best = -1.0f;
                #pragma unroll
                for (int a = 0; a < AA; a++) {
                    float inter = fminf(gw, c_aw[a]) * fminf(gh, c_ah[a]);
                    float uni   = gw * gh + c_aw[a] * c_ah[a] - inter;
                    float rr    = inter / uni;
                    if (rr > best) { best = rr; ba = a; }
                }

                int gi = (int)gx; gi = gi < 0 ? 0 : (gi > WW - 1 ? WW - 1 : gi);
                int gj = (int)gy; gj = gj < 0 ? 0 : (gj > HH - 1 ? HH - 1 : gj);

                const float* pb = pred + ((size_t)(b * AA + ba) * CH) * HW + gj * WW + gi;
                const float bx = sigmoidf_(pb[0]) + (float)gi;
                const float by = sigmoidf_(pb[HW]) + (float)gj;
                const float bw = __expf(pb[2 * HW]) * c_aw[ba];
                const float bh = __expf(pb[3 * HW]) * c_ah[ba];

                const float iw = fmaxf(fminf(gx + 0.5f * gw, bx + 0.5f * bw) -
                                       fmaxf(gx - 0.5f * gw, bx - 0.5f * bw), 0.0f);
                const float ih = fmaxf(fminf(gy + 0.5f * gh, by + 0.5f * bh) -
                                       fmaxf(gy - 0.5f * gh, by - 0.5f * bh), 0.0f);
                const float inter = iw * ih;
                const float uni   = gw * gh + bw * bh - inter;

                s_cell[tid] = ba * HW + gj * WW + gi;
                s_tbox[tid] = make_float4(gx - (float)gi, gy - (float)gj,
                                          __logf(gw / c_aw[ba]), __logf(gh / c_ah[ba]));
                s_iou[tid]  = inter / uni;
                int tc = (int)t[0]; tc = tc < 0 ? 0 : (tc > CC - 1 ? CC - 1 : tc);
                s_cls[tid]  = tc;
            } else {
                s_cell[tid] = -1;
                s_box[tid]  = make_float4(1e30f, 1e30f, -1e30f, -1e30f);
                s_a375[tid] = 1e30f;
            }
        }
        __syncthreads();

        // ---- Phase 2: parallel last-writer-wins dedup ----
        if (tid < NBOX) {
            const int mycell = s_cell[tid];
            bool win = (mycell >= 0);
            if (win) {
                for (int j = tid + 1; j < NBOX; j++) win &= (s_cell[j] != mycell);
            }
            s_win[tid] = win ? 1 : 0;
        }
        __syncthreads();

        // ---- Phase 3: correction; this block handles rid % SCAT_SPLIT == sub,
        //      8 warps stride within that subset (~1-2 records per warp) ----
        float acc = 0.0f;
        for (int rid = sub + SCAT_SPLIT * warp; rid < NBOX;
             rid += SCAT_SPLIT * (BLK / 32)) {
            if (!s_win[rid]) continue;

            const int cell = s_cell[rid];
            const int a  = cell / HW;
            const int r  = cell % HW;

            const float* pb = pred + ((size_t)(b * AA + a) * CH) * HW + r;
            const float q2 = pb[2 * HW], q3 = pb[3 * HW];
            const float sx = sigmoidf_(pb[0]), sy = sigmoidf_(pb[HW]);
            const float cf = sigmoidf_(pb[4 * HW]);
            const float bw = __expf(q2) * c_aw[a], bh = __expf(q3) * c_ah[a];
            const float bx = sx + (float)(r % WW), by = sy + (float)(r / WW);

            const float px1 = bx - 0.5f * bw, px2 = bx + 0.5f * bw;
            const float py1 = by - 0.5f * bh, py2 = by + 0.5f * bh;
            const float t0  = 0.375f * (bw * bh);

            // silence test (identical arithmetic to hot role)
            float m = -1e30f;
            for (int n = lane; n < NBOX; n += 32) {
                const float4 g = s_box[n];
                float iw = fminf(px2, g.z) - fmaxf(px1, g.x);
                float ih = fminf(py2, g.w) - fmaxf(py1, g.y);
                m = fmaxf(m, __fmaf_rn(fmaxf(iw, 0.0f), fmaxf(ih, 0.0f), -s_a375[n]));
            }
            m = warpReduceMax(m);
            const float mask_def = (m > t0) ? 0.0f : 1.0f;

            const float dx0 = sx - 0.5f, dy0 = sy - 0.5f;
            const float v_def = 0.5f * (dx0 * dx0 + dy0 * dy0 + q2 * q2 + q3 * q3 +
                                        cf * cf * mask_def);

            const float4 tb   = s_tbox[rid];
            const float  tcnf = s_iou[rid];
            const int    tc   = s_cls[rid];

            // 80-way log-softmax CE, lanes stride classes
            const float* cl = pb + 5 * HW;
            float mx = -1e30f;
            for (int c = lane; c < CC; c += 32) mx = fmaxf(mx, cl[c * HW]);
            mx = warpReduceMax(mx);
            float s = 0.0f;
            for (int c = lane; c < CC; c += 32) s += __expf(cl[c * HW] - mx);
            s = warpReduceSum(s);
            const float ce = mx + __logf(s) - cl[tc * HW];

            const float dx = sx - tb.x, dy = sy - tb.y;
            const float dw = q2 - tb.z, dh = q3 - tb.w;
            const float dc = cf - tcnf;
            const float v_true = 0.5f * (dx * dx + dy * dy + dw * dw + dh * dh +
                                         dc * dc * 5.0f) + ce;

            if (lane == 0) acc += v_true - v_def;
        }

        float wv = warpReduceSum(acc);
        if (lane == 0) s_red[warp] = wv;
        __syncthreads();
        if (warp == 0) {
            float bv = (lane < (BLK / 32)) ? s_red[lane] : 0.0f;
            bv = warpReduceSum(bv);
            if (lane == 0) atomicAdd(out, bv);
        }
        return;
    }

    // ===================== ROLE B: default-target loss =====================
    const int gid   = blockIdx.x - SCAT_BLOCKS;
    const int b     = gid / HOT_BLOCKS_PER_B;
    const int chunk = gid % HOT_BLOCKS_PER_B;

    if (tid < NBOX) {
        const float* t = target + (size_t)(b * NBOX + tid) * 5;
        float x = t[1] * WW, y = t[2] * HH, w = t[3] * WW, h = t[4] * HH;
        if (t[1] > 0.0f) {
            s_box[tid]  = make_float4(x - 0.5f * w, y - 0.5f * h,
                                      x + 0.5f * w, y + 0.5f * h);
            s_a375[tid] = 0.375f * (w * h);
        } else {
            s_box[tid]  = make_float4(1e30f, 1e30f, -1e30f, -1e30f);
            s_a375[tid] = 1e30f;
        }
    }
    __syncthreads();

    const int base = chunk * CELLS_PER_BLK;

    const int idx0 = base + tid;
    const int idx1 = base + tid + BLK;
    const bool ok0 = idx0 < NCELL_PER_B;
    const bool ok1 = idx1 < NCELL_PER_B;
    const int ci0 = ok0 ? idx0 : 0;
    const int ci1 = ok1 ? idx1 : 0;

    const int a0 = ci0 / HW, r0 = ci0 % HW;
    const int a1 = ci1 / HW, r1 = ci1 % HW;

    const float* pb0 = pred + ((size_t)(b * AA + a0) * CH) * HW + r0;
    const float* pb1 = pred + ((size_t)(b * AA + a1) * CH) * HW + r1;

    const float q02 = pb0[2 * HW], q03 = pb0[3 * HW];
    const float q12 = pb1[2 * HW], q13 = pb1[3 * HW];

    const float sx0 = sigmoidf_(pb0[0]), sy0 = sigmoidf_(pb0[HW]);
    const float sx1 = sigmoidf_(pb1[0]), sy1 = sigmoidf_(pb1[HW]);
    const float cf0 = sigmoidf_(pb0[4 * HW]);
    const float cf1 = sigmoidf_(pb1[4 * HW]);

    const float bw0 = __expf(q02) * c_aw[a0], bh0 = __expf(q03) * c_ah[a0];
    const float bw1 = __expf(q12) * c_aw[a1], bh1 = __expf(q13) * c_ah[a1];

    const float bx0 = sx0 + (float)(r0 % WW), by0 = sy0 + (float)(r0 / WW);
    const float bx1 = sx1 + (float)(r1 % WW), by1 = sy1 + (float)(r1 / WW);

    const float px1_0 = bx0 - 0.5f * bw0, px2_0 = bx0 + 0.5f * bw0;
    const float py1_0 = by0 - 0.5f * bh0, py2_0 = by0 + 0.5f * bh0;
    const float px1_1 = bx1 - 0.5f * bw1, px2_1 = bx1 + 0.5f * bw1;
    const float py1_1 = by1 - 0.5f * bh1, py2_1 = by1 + 0.5f * bh1;
    const float t0_0 = 0.375f * (bw0 * bh0);
    const float t0_1 = 0.375f * (bw1 * bh1);

    float m0 = -1e30f, m1 = -1e30f;
    #pragma unroll 25
    for (int n = 0; n < NBOX; n++) {
        const float4 g  = s_box[n];     // (x1, y1, x2, y2)
        const float  an = s_a375[n];

        float iw0 = fminf(px2_0, g.z) - fmaxf(px1_0, g.x);
        float ih0 = fminf(py2_0, g.w) - fmaxf(py1_0, g.y);
        m0 = fmaxf(m0, __fmaf_rn(fmaxf(iw0, 0.0f), fmaxf(ih0, 0.0f), -an));

        float iw1 = fminf(px2_1, g.z) - fmaxf(px1_1, g.x);
        float ih1 = fminf(py2_1, g.w) - fmaxf(py1_1, g.y);
        m1 = fmaxf(m1, __fmaf_rn(fmaxf(iw1, 0.0f), fmaxf(ih1, 0.0f), -an));
    }

    float v = 0.0f;
    if (ok0) {
        const float mask = (m0 > t0_0) ? 0.0f : 1.0f;
        const float dx = sx0 - 0.5f, dy = sy0 - 0.5f;
        v += 0.5f * (dx * dx + dy * dy + q02 * q02 + q03 * q03 + cf0 * cf0 * mask);
    }
    if (ok1) {
        const float mask = (m1 > t0_1) ? 0.0f : 1.0f;
        const float dx = sx1 - 0.5f, dy = sy1 - 0.5f;
        v += 0.5f * (dx * dx + dy * dy + q12 * q12 + q13 * q13 + cf1 * cf1 * mask);
    }

    float wv = warpReduceSum(v);
    if (lane == 0) s_red[warp] = wv;
    __syncthreads();
    if (warp == 0) {
        float bv = (lane < (BLK / 32)) ? s_red[lane] : 0.0f;
        bv = warpReduceSum(bv);
        if (lane == 0) atomicAdd(out, bv);
    }
}

extern "C" void kernel_launch(void* const* d_in, const int* in_sizes, int n_in,
                              void* d_out, int out_size)
{
    const float* pred   = (const float*)d_in[0];
    const float* target = (const float*)d_in[1];
    float* out = (float*)d_out;

    cudaMemsetAsync(out, 0, (size_t)out_size * sizeof(float));
    region_loss_kernel<<<TOTAL_BLOCKS, BLK>>>(pred, target, out);
}